// round 6
// baseline (speedup 1.0000x reference)
#include <cuda_runtime.h>
#include <cstdint>
#include <math.h>

#define T  2048
#define HD 1024
#define ID 512
#define NE 32

// ---------------- scratch (device globals: allocation-free) ----------------
__device__ int   g_cnt[NE];
__device__ int   g_tok[NE * T];
__device__ float g_wt [NE * T];
__device__ float g_inter   [(size_t)NE * T * ID];
__device__ float g_inter_sh[(size_t)T * HD];
// tf32-preconverted operands
__device__ float g_wg [(size_t)NE * ID * HD];
__device__ float g_wu [(size_t)NE * ID * HD];
__device__ float g_wd [(size_t)NE * HD * ID];
__device__ float g_shg[(size_t)2 * ID * HD];
__device__ float g_shu[(size_t)2 * ID * HD];
__device__ float g_shd[(size_t)HD * 2 * ID];
__device__ float g_hc [(size_t)T * HD];

// ---------------- helpers ----------------
__device__ __forceinline__ uint32_t smem_u32(const void* p) {
    uint32_t a;
    asm("{ .reg .u64 t; cvta.to.shared.u64 t, %1; cvt.u32.u64 %0, t; }" : "=r"(a) : "l"(p));
    return a;
}
__device__ __forceinline__ uint32_t to_tf32(float f) {
    uint32_t r;
    asm("cvt.rna.tf32.f32 %0, %1;" : "=r"(r) : "f"(f));
    return r;
}
__device__ __forceinline__ void mma_tf32(float* c, const uint32_t* a, const uint32_t* b) {
    asm volatile(
        "mma.sync.aligned.m16n8k8.row.col.f32.tf32.tf32.f32 "
        "{%0,%1,%2,%3}, {%4,%5,%6,%7}, {%8,%9}, {%0,%1,%2,%3};"
        : "+f"(c[0]), "+f"(c[1]), "+f"(c[2]), "+f"(c[3])
        : "r"(a[0]), "r"(a[1]), "r"(a[2]), "r"(a[3]), "r"(b[0]), "r"(b[1]));
}
__device__ __forceinline__ float silu(float g) {
    return g / (1.f + __expf(-g));
}
#define CP16(dst, src) asm volatile("cp.async.cg.shared.global [%0], [%1], 16;" :: "r"(dst), "l"(src))
#define CP_COMMIT()    asm volatile("cp.async.commit_group;" ::: "memory")
#define CP_WAIT(n)     asm volatile("cp.async.wait_group %0;" :: "n"(n) : "memory")
#define LDSM4(r0, r1, r2, r3, addr) \
    asm volatile("ldmatrix.sync.aligned.m8n8.x4.shared.b16 {%0,%1,%2,%3}, [%4];" \
        : "=r"(r0), "=r"(r1), "=r"(r2), "=r"(r3) : "r"(addr))

// ---------------- tf32 pre-conversion ----------------
__global__ void cvt_tf32_kernel(const float4* __restrict__ src,
                                float4* __restrict__ dst, int n4) {
    int i = blockIdx.x * blockDim.x + threadIdx.x;
    int stride = gridDim.x * blockDim.x;
    for (; i < n4; i += stride) {
        float4 v = src[i];
        float4 o;
        o.x = __uint_as_float(to_tf32(v.x));
        o.y = __uint_as_float(to_tf32(v.y));
        o.z = __uint_as_float(to_tf32(v.z));
        o.w = __uint_as_float(to_tf32(v.w));
        dst[i] = o;
    }
}

// ---------------- zero counters ----------------
__global__ void zero_kernel() {
    if (threadIdx.x < NE) g_cnt[threadIdx.x] = 0;
}

// ---------------- router: 1 warp per token ----------------
__global__ void router_kernel(const float* __restrict__ h,
                              const float* __restrict__ gw,
                              const float* __restrict__ gb) {
    __shared__ float s_sc[4][32];
    __shared__ float s_ss[4][32];
    int wid  = threadIdx.x >> 5;
    int lane = threadIdx.x & 31;
    int t = blockIdx.x * 4 + wid;
    if (t >= T) return;

    const float4* hv = (const float4*)(h + (size_t)t * HD);
    const float4* wv = (const float4*)(gw + (size_t)lane * HD);
    float acc = 0.f;
#pragma unroll 8
    for (int j = 0; j < HD / 4; j++) {
        float4 a = hv[j]; float4 b = wv[j];
        acc += a.x * b.x + a.y * b.y + a.z * b.z + a.w * b.w;
    }
    float score = 1.f / (1.f + expf(-acc));
    s_ss[wid][lane] = score;
    s_sc[wid][lane] = score + gb[lane];
    __syncwarp();

    if (lane == 0) {
        float* SC = s_sc[wid];
        float* SS = s_ss[wid];
        float gs[8];
#pragma unroll
        for (int g = 0; g < 8; g++) {
            float m1 = -1e30f, m2 = -1e30f;
#pragma unroll
            for (int q = 0; q < 4; q++) {
                float v = SC[g * 4 + q];
                if (v > m1) { m2 = m1; m1 = v; }
                else if (v > m2) m2 = v;
            }
            gs[g] = m1 + m2;
        }
        unsigned gsel = 0;
        for (int it = 0; it < 4; it++) {
            float best = -1e30f; int bi = 0;
            for (int g = 0; g < 8; g++)
                if (!((gsel >> g) & 1) && gs[g] > best) { best = gs[g]; bi = g; }
            gsel |= 1u << bi;
        }
        float masked[32];
#pragma unroll
        for (int e = 0; e < 32; e++)
            masked[e] = ((gsel >> (e >> 2)) & 1) ? SC[e] : 0.f;
        int tki[8]; float tw[8];
        unsigned used = 0;
        for (int k = 0; k < 8; k++) {
            float best = -1e30f; int bi = 0;
            for (int e = 0; e < 32; e++)
                if (!((used >> e) & 1) && masked[e] > best) { best = masked[e]; bi = e; }
            used |= 1u << bi;
            tki[k] = bi;
            tw[k] = SS[bi];
        }
        float s = 1e-20f;
        for (int k = 0; k < 8; k++) s += tw[k];
        float inv = 2.5f / s;
        for (int k = 0; k < 8; k++) {
            int e = tki[k];
            int pos = atomicAdd(&g_cnt[e], 1);
            g_tok[e * T + pos] = t;
            g_wt [e * T + pos] = tw[k] * inv;
        }
    }
}

// ============================================================================
// GEMM tiles: BM=128, BN=64, BK=32, 256 threads = 8 warps, 2 blocks/SM.
// All operands pre-converted to tf32. Fragments via ldmatrix.x4.b16 on fp32
// data (4 consecutive fp32 = one 16B ldmatrix row). cp.async double buffer.
// Smem word stride 36 -> conflict-free ldmatrix row addresses.
// ============================================================================
#define ASTR 36
#define GU_STAGE_W   9216            // A 4608 + Bg 2304 + Bu 2304 words
#define GU_SMEM      (2 * GU_STAGE_W * 4)
#define DN_STAGE_W   6912            // A 4608 + B 2304 words
#define DN_SMEM      (2 * DN_STAGE_W * 4)

// ---- gate+up (fused) + silu (epilogue rounds to tf32 for the down GEMM) ----
template<int ROUTED>
__global__ void __launch_bounds__(256, 2)
gu_mma(const float* __restrict__ h,
       const float* __restrict__ Wg,
       const float* __restrict__ Wu)
{
    constexpr int KD = HD;
    constexpr int NT = KD / 32;
    int e   = ROUTED ? blockIdx.z : 0;
    int cnt = ROUTED ? g_cnt[e] : T;
    int m0  = blockIdx.y * 128;
    if (m0 >= cnt) return;
    int n0  = blockIdx.x * 64;

    extern __shared__ float smem[];
    uint32_t smem_b = smem_u32(smem);
    __shared__ int s_tok[128];

    int tid  = threadIdx.x;
    int wid  = tid >> 5;
    int lane = tid & 31;
    int wm   = wid & 3;
    int wn   = wid >> 2;

    if (ROUTED && tid < 128) {
        int m = m0 + tid;
        s_tok[tid] = (m < cnt) ? g_tok[e * T + m] : g_tok[e * T];
    }
    __syncthreads();

    const float* Bg0 = Wg + (ROUTED ? (size_t)e * ID * HD : 0) + (size_t)n0 * KD;
    const float* Bu0 = Wu + (ROUTED ? (size_t)e * ID * HD : 0) + (size_t)n0 * KD;

    int a_row = tid >> 1;
    int a_c4  = (tid & 1) * 4;
    const float* a_src;
    if (ROUTED) a_src = h + (size_t)s_tok[a_row] * HD;
    else        a_src = h + (size_t)(m0 + a_row) * HD;
    int b_row = tid >> 2;
    int b_c4  = (tid & 3) * 2;
    const float* bg_src = Bg0 + (size_t)b_row * KD;
    const float* bu_src = Bu0 + (size_t)b_row * KD;

    uint32_t a_dst = smem_b + (uint32_t)a_row * 144u + (uint32_t)a_c4 * 16u;
    uint32_t g_dst = smem_b + 18432u + (uint32_t)b_row * 144u + (uint32_t)b_c4 * 16u;
    uint32_t u_dst = smem_b + 27648u + (uint32_t)b_row * 144u + (uint32_t)b_c4 * 16u;

#define GU_COPY(st, k0) do { \
    uint32_t off = (uint32_t)(st) * (GU_STAGE_W * 4); \
    const float* ap = a_src  + (k0) + a_c4 * 4; \
    const float* gp = bg_src + (k0) + b_c4 * 4; \
    const float* up = bu_src + (k0) + b_c4 * 4; \
    CP16(a_dst + off,      ap);      CP16(a_dst + off + 16, ap + 4); \
    CP16(a_dst + off + 32, ap + 8);  CP16(a_dst + off + 48, ap + 12); \
    CP16(g_dst + off,      gp);      CP16(g_dst + off + 16, gp + 4); \
    CP16(u_dst + off,      up);      CP16(u_dst + off + 16, up + 4); \
} while (0)

    // ldmatrix per-lane row addresses (byte offsets within a stage)
    int lr = lane & 7, lg = lane >> 3;
    uint32_t a_off[2];
#pragma unroll
    for (int mi = 0; mi < 2; mi++) {
        int row = wm * 32 + mi * 16 + (lg & 1) * 8 + lr;
        a_off[mi] = (uint32_t)((row * ASTR + (lg >> 1) * 4) * 4);
    }
    uint32_t bg_off[2], bu_off[2];
#pragma unroll
    for (int p = 0; p < 2; p++) {
        int row = wn * 32 + p * 16 + (lg >> 1) * 8 + lr;
        int koff = (lg & 1) * 4;
        bg_off[p] = (uint32_t)((4608 + row * ASTR + koff) * 4);
        bu_off[p] = (uint32_t)((6912 + row * ASTR + koff) * 4);
    }

    float cg[2][4][4] = {}, cu[2][4][4] = {};

    GU_COPY(0, 0);
    CP_COMMIT();

    for (int kt = 0; kt < NT; kt++) {
        if (kt + 1 < NT) {
            GU_COPY((kt + 1) & 1, (kt + 1) * 32);
            CP_COMMIT();
            CP_WAIT(1);
        } else {
            CP_WAIT(0);
        }
        __syncthreads();

        uint32_t sb = smem_b + (uint32_t)(kt & 1) * (GU_STAGE_W * 4);

#pragma unroll
        for (int ks = 0; ks < 4; ks++) {
            uint32_t kb = (uint32_t)ks * 32u;
            uint32_t af[2][4];
            LDSM4(af[0][0], af[0][1], af[0][2], af[0][3], sb + a_off[0] + kb);
            LDSM4(af[1][0], af[1][1], af[1][2], af[1][3], sb + a_off[1] + kb);
            uint32_t bgf[4][2], buf_[4][2];
            LDSM4(bgf[0][0], bgf[0][1], bgf[1][0], bgf[1][1], sb + bg_off[0] + kb);
            LDSM4(bgf[2][0], bgf[2][1], bgf[3][0], bgf[3][1], sb + bg_off[1] + kb);
            LDSM4(buf_[0][0], buf_[0][1], buf_[1][0], buf_[1][1], sb + bu_off[0] + kb);
            LDSM4(buf_[2][0], buf_[2][1], buf_[3][0], buf_[3][1], sb + bu_off[1] + kb);
#pragma unroll
            for (int mi = 0; mi < 2; mi++)
#pragma unroll
                for (int ni = 0; ni < 4; ni++) {
                    mma_tf32(cg[mi][ni], af[mi], bgf[ni]);
                    mma_tf32(cu[mi][ni], af[mi], buf_[ni]);
                }
        }
        __syncthreads();
    }
#undef GU_COPY

    // epilogue: silu(g)*u, rounded to tf32 (identical to cvt-at-load numerics)
    int gr = lane >> 2;
    int gc = (lane & 3) * 2;
    constexpr int OD = ROUTED ? ID : HD;
    float* obase;
    if (ROUTED) obase = g_inter + ((size_t)e * T + m0) * OD;
    else        obase = g_inter_sh + (size_t)m0 * OD;

#pragma unroll
    for (int mi = 0; mi < 2; mi++) {
        int mA = wm * 32 + mi * 16 + gr;
        int mB = mA + 8;
        bool vA = (m0 + mA) < cnt;
        bool vB = (m0 + mB) < cnt;
#pragma unroll
        for (int ni = 0; ni < 4; ni++) {
            int n = n0 + wn * 32 + ni * 8 + gc;
            float* c = cg[mi][ni];
            float* d = cu[mi][ni];
            if (vA) {
                float2 o = make_float2(
                    __uint_as_float(to_tf32(silu(c[0]) * d[0])),
                    __uint_as_float(to_tf32(silu(c[1]) * d[1])));
                *(float2*)(obase + (size_t)mA * OD + n) = o;
            }
            if (vB) {
                float2 o = make_float2(
                    __uint_as_float(to_tf32(silu(c[2]) * d[2])),
                    __uint_as_float(to_tf32(silu(c[3]) * d[3])));
                *(float2*)(obase + (size_t)mB * OD + n) = o;
            }
        }
    }
}

// ---- down-proj ----
template<int ROUTED>
__global__ void __launch_bounds__(256, 2)
down_mma(const float* __restrict__ Wd, float* __restrict__ out)
{
    constexpr int KD = ROUTED ? ID : HD;
    constexpr int NT = KD / 32;
    int e   = ROUTED ? blockIdx.z : 0;
    int cnt = ROUTED ? g_cnt[e] : T;
    int m0  = blockIdx.y * 128;
    if (m0 >= cnt) return;
    int n0  = blockIdx.x * 64;

    extern __shared__ float smem[];
    uint32_t smem_b = smem_u32(smem);
    __shared__ int   s_tok[128];
    __shared__ float s_w[128];

    int tid  = threadIdx.x;
    int wid  = tid >> 5;
    int lane = tid & 31;
    int wm   = wid & 3;
    int wn   = wid >> 2;

    if (ROUTED && tid < 128) {
        int m = m0 + tid;
        s_tok[tid] = (m < cnt) ? g_tok[e * T + m] : 0;
        s_w[tid]   = (m < cnt) ? g_wt [e * T + m] : 0.f;
    }
    __syncthreads();

    const float* A0 = ROUTED ? (g_inter + ((size_t)e * T + m0) * KD)
                             : (g_inter_sh + (size_t)m0 * KD);
    const float* B0 = Wd + (ROUTED ? (size_t)e * HD * ID : 0) + (size_t)n0 * KD;

    int a_row = tid >> 1;
    int a_c4  = (tid & 1) * 4;
    const float* a_src = A0 + (size_t)a_row * KD;
    int b_row = tid >> 2;
    int b_c4  = (tid & 3) * 2;
    const float* b_src = B0 + (size_t)b_row * KD;

    uint32_t a_dst = smem_b + (uint32_t)a_row * 144u + (uint32_t)a_c4 * 16u;
    uint32_t b_dst = smem_b + 18432u + (uint32_t)b_row * 144u + (uint32_t)b_c4 * 16u;

#define DN_COPY(st, k0) do { \
    uint32_t off = (uint32_t)(st) * (DN_STAGE_W * 4); \
    const float* ap = a_src + (k0) + a_c4 * 4; \
    const float* bp = b_src + (k0) + b_c4 * 4; \
    CP16(a_dst + off,      ap);      CP16(a_dst + off + 16, ap + 4); \
    CP16(a_dst + off + 32, ap + 8);  CP16(a_dst + off + 48, ap + 12); \
    CP16(b_dst + off,      bp);      CP16(b_dst + off + 16, bp + 4); \
} while (0)

    int lr = lane & 7, lg = lane >> 3;
    uint32_t a_off[2];
#pragma unroll
    for (int mi = 0; mi < 2; mi++) {
        int row = wm * 32 + mi * 16 + (lg & 1) * 8 + lr;
        a_off[mi] = (uint32_t)((row * ASTR + (lg >> 1) * 4) * 4);
    }
    uint32_t bs_off[2];
#pragma unroll
    for (int p = 0; p < 2; p++) {
        int row = wn * 32 + p * 16 + (lg >> 1) * 8 + lr;
        int koff = (lg & 1) * 4;
        bs_off[p] = (uint32_t)((4608 + row * ASTR + koff) * 4);
    }

    float cc[2][4][4] = {};

    DN_COPY(0, 0);
    CP_COMMIT();

    for (int kt = 0; kt < NT; kt++) {
        if (kt + 1 < NT) {
            DN_COPY((kt + 1) & 1, (kt + 1) * 32);
            CP_COMMIT();
            CP_WAIT(1);
        } else {
            CP_WAIT(0);
        }
        __syncthreads();

        uint32_t sb = smem_b + (uint32_t)(kt & 1) * (DN_STAGE_W * 4);

#pragma unroll
        for (int ks = 0; ks < 4; ks++) {
            uint32_t kb = (uint32_t)ks * 32u;
            uint32_t af[2][4];
            LDSM4(af[0][0], af[0][1], af[0][2], af[0][3], sb + a_off[0] + kb);
            LDSM4(af[1][0], af[1][1], af[1][2], af[1][3], sb + a_off[1] + kb);
            uint32_t bf[4][2];
            LDSM4(bf[0][0], bf[0][1], bf[1][0], bf[1][1], sb + bs_off[0] + kb);
            LDSM4(bf[2][0], bf[2][1], bf[3][0], bf[3][1], sb + bs_off[1] + kb);
#pragma unroll
            for (int mi = 0; mi < 2; mi++)
#pragma unroll
                for (int ni = 0; ni < 4; ni++)
                    mma_tf32(cc[mi][ni], af[mi], bf[ni]);
        }
        __syncthreads();
    }
#undef DN_COPY

    int gr = lane >> 2;
    int gc = (lane & 3) * 2;

#pragma unroll
    for (int mi = 0; mi < 2; mi++) {
        int mA = wm * 32 + mi * 16 + gr;
        int mB = mA + 8;
        bool vA = (m0 + mA) < cnt;
        bool vB = (m0 + mB) < cnt;
#pragma unroll
        for (int ni = 0; ni < 4; ni++) {
            int n = n0 + wn * 32 + ni * 8 + gc;
            float* c = cc[mi][ni];
            if (ROUTED) {
                if (vA) {
                    float w = s_w[mA];
                    float* p = out + (size_t)s_tok[mA] * HD + n;
                    atomicAdd(p,     c[0] * w);
                    atomicAdd(p + 1, c[1] * w);
                }
                if (vB) {
                    float w = s_w[mB];
                    float* p = out + (size_t)s_tok[mB] * HD + n;
                    atomicAdd(p,     c[2] * w);
                    atomicAdd(p + 1, c[3] * w);
                }
            } else {
                *(float2*)(out + (size_t)(m0 + mA) * HD + n) = make_float2(c[0], c[1]);
                *(float2*)(out + (size_t)(m0 + mB) * HD + n) = make_float2(c[2], c[3]);
            }
        }
    }
}

// ---------------- launch ----------------
extern "C" void kernel_launch(void* const* d_in, const int* in_sizes, int n_in,
                              void* d_out, int out_size) {
    const float* h       = (const float*)d_in[0];
    const float* gate_w  = (const float*)d_in[1];
    const float* gate_b  = (const float*)d_in[2];
    const float* w_gate  = (const float*)d_in[3];
    const float* w_up    = (const float*)d_in[4];
    const float* w_down  = (const float*)d_in[5];
    const float* sh_gate = (const float*)d_in[6];
    const float* sh_up   = (const float*)d_in[7];
    const float* sh_down = (const float*)d_in[8];
    float* out = (float*)d_out;

    cudaFuncSetAttribute(gu_mma<1>,   cudaFuncAttributeMaxDynamicSharedMemorySize, GU_SMEM);
    cudaFuncSetAttribute(gu_mma<0>,   cudaFuncAttributeMaxDynamicSharedMemorySize, GU_SMEM);
    cudaFuncSetAttribute(down_mma<1>, cudaFuncAttributeMaxDynamicSharedMemorySize, DN_SMEM);
    cudaFuncSetAttribute(down_mma<0>, cudaFuncAttributeMaxDynamicSharedMemorySize, DN_SMEM);

    float *p_wg, *p_wu, *p_wd, *p_shg, *p_shu, *p_shd, *p_hc;
    cudaGetSymbolAddress((void**)&p_wg,  g_wg);
    cudaGetSymbolAddress((void**)&p_wu,  g_wu);
    cudaGetSymbolAddress((void**)&p_wd,  g_wd);
    cudaGetSymbolAddress((void**)&p_shg, g_shg);
    cudaGetSymbolAddress((void**)&p_shu, g_shu);
    cudaGetSymbolAddress((void**)&p_shd, g_shd);
    cudaGetSymbolAddress((void**)&p_hc,  g_hc);

    zero_kernel<<<1, 32>>>();
    router_kernel<<<T / 4, 128>>>(h, gate_w, gate_b);

    const int NW4 = NE * ID * HD / 4;   // 4194304
    const int NS4 = 2 * ID * HD / 4;    // 262144
    const int NH4 = T * HD / 4;         // 524288
    cvt_tf32_kernel<<<2048, 256>>>((const float4*)w_gate,  (float4*)p_wg,  NW4);
    cvt_tf32_kernel<<<2048, 256>>>((const float4*)w_up,    (float4*)p_wu,  NW4);
    cvt_tf32_kernel<<<2048, 256>>>((const float4*)w_down,  (float4*)p_wd,  NW4);
    cvt_tf32_kernel<<<512,  256>>>((const float4*)sh_gate, (float4*)p_shg, NS4);
    cvt_tf32_kernel<<<512,  256>>>((const float4*)sh_up,   (float4*)p_shu, NS4);
    cvt_tf32_kernel<<<512,  256>>>((const float4*)sh_down, (float4*)p_shd, NS4);
    cvt_tf32_kernel<<<1024, 256>>>((const float4*)h,       (float4*)p_hc,  NH4);

    // routed gate+up: N=512 -> 8 n-tiles, M tiles over cnt (early exit)
    gu_mma<1><<<dim3(ID / 64, T / 128, NE), 256, GU_SMEM>>>(p_hc, p_wg, p_wu);
    // shared gate+up: N=1024 -> 16 n-tiles
    gu_mma<0><<<dim3((2 * ID) / 64, T / 128, 1), 256, GU_SMEM>>>(p_hc, p_shg, p_shu);
    // shared down-proj writes out (covers poison)
    down_mma<0><<<dim3(HD / 64, T / 128, 1), 256, DN_SMEM>>>(p_shd, out);
    // routed down-proj accumulates
    down_mma<1><<<dim3(HD / 64, T / 128, NE), 256, DN_SMEM>>>(p_wd, out);
}

// round 7
// speedup vs baseline: 1.0396x; 1.0396x over previous
#include <cuda_runtime.h>
#include <cstdint>
#include <math.h>

#define T  2048
#define HD 1024
#define ID 512
#define NE 32

// ---------------- scratch (device globals: allocation-free) ----------------
__device__ int   g_cnt[NE];
__device__ int   g_tok[NE * T];
__device__ float g_wt [NE * T];
__device__ float g_inter   [(size_t)NE * T * ID];
__device__ float g_inter_sh[(size_t)T * HD];
// tf32-preconverted operands
__device__ float g_wg [(size_t)NE * ID * HD];
__device__ float g_wu [(size_t)NE * ID * HD];
__device__ float g_wd [(size_t)NE * HD * ID];
__device__ float g_shg[(size_t)2 * ID * HD];
__device__ float g_shu[(size_t)2 * ID * HD];
__device__ float g_shd[(size_t)HD * 2 * ID];
__device__ float g_hc [(size_t)T * HD];

// ---------------- helpers ----------------
__device__ __forceinline__ uint32_t smem_u32(const void* p) {
    uint32_t a;
    asm("{ .reg .u64 t; cvta.to.shared.u64 t, %1; cvt.u32.u64 %0, t; }" : "=r"(a) : "l"(p));
    return a;
}
__device__ __forceinline__ uint32_t to_tf32(float f) {
    uint32_t r;
    asm("cvt.rna.tf32.f32 %0, %1;" : "=r"(r) : "f"(f));
    return r;
}
__device__ __forceinline__ void mma_tf32(float* c, const uint32_t* a, const uint32_t* b) {
    asm volatile(
        "mma.sync.aligned.m16n8k8.row.col.f32.tf32.tf32.f32 "
        "{%0,%1,%2,%3}, {%4,%5,%6,%7}, {%8,%9}, {%0,%1,%2,%3};"
        : "+f"(c[0]), "+f"(c[1]), "+f"(c[2]), "+f"(c[3])
        : "r"(a[0]), "r"(a[1]), "r"(a[2]), "r"(a[3]), "r"(b[0]), "r"(b[1]));
}
__device__ __forceinline__ float silu(float g) {
    return g / (1.f + __expf(-g));
}
#define CP16(dst, src) asm volatile("cp.async.cg.shared.global [%0], [%1], 16;" :: "r"(dst), "l"(src))
#define CP_COMMIT()    asm volatile("cp.async.commit_group;" ::: "memory")
#define CP_WAIT(n)     asm volatile("cp.async.wait_group %0;" :: "n"(n) : "memory")
#define LDSM4(r0, r1, r2, r3, addr) \
    asm volatile("ldmatrix.sync.aligned.m8n8.x4.shared.b16 {%0,%1,%2,%3}, [%4];" \
        : "=r"(r0), "=r"(r1), "=r"(r2), "=r"(r3) : "r"(addr))

// ---------------- tf32 pre-conversion ----------------
__global__ void cvt_tf32_kernel(const float4* __restrict__ src,
                                float4* __restrict__ dst, int n4) {
    int i = blockIdx.x * blockDim.x + threadIdx.x;
    int stride = gridDim.x * blockDim.x;
    for (; i < n4; i += stride) {
        float4 v = src[i];
        float4 o;
        o.x = __uint_as_float(to_tf32(v.x));
        o.y = __uint_as_float(to_tf32(v.y));
        o.z = __uint_as_float(to_tf32(v.z));
        o.w = __uint_as_float(to_tf32(v.w));
        dst[i] = o;
    }
}

// ---------------- zero counters ----------------
__global__ void zero_kernel() {
    if (threadIdx.x < NE) g_cnt[threadIdx.x] = 0;
}

// ---------------- router: 1 warp per token ----------------
__global__ void router_kernel(const float* __restrict__ h,
                              const float* __restrict__ gw,
                              const float* __restrict__ gb) {
    __shared__ float s_sc[4][32];
    __shared__ float s_ss[4][32];
    int wid  = threadIdx.x >> 5;
    int lane = threadIdx.x & 31;
    int t = blockIdx.x * 4 + wid;
    if (t >= T) return;

    const float4* hv = (const float4*)(h + (size_t)t * HD);
    const float4* wv = (const float4*)(gw + (size_t)lane * HD);
    float acc = 0.f;
#pragma unroll 8
    for (int j = 0; j < HD / 4; j++) {
        float4 a = hv[j]; float4 b = wv[j];
        acc += a.x * b.x + a.y * b.y + a.z * b.z + a.w * b.w;
    }
    float score = 1.f / (1.f + expf(-acc));
    s_ss[wid][lane] = score;
    s_sc[wid][lane] = score + gb[lane];
    __syncwarp();

    if (lane == 0) {
        float* SC = s_sc[wid];
        float* SS = s_ss[wid];
        float gs[8];
#pragma unroll
        for (int g = 0; g < 8; g++) {
            float m1 = -1e30f, m2 = -1e30f;
#pragma unroll
            for (int q = 0; q < 4; q++) {
                float v = SC[g * 4 + q];
                if (v > m1) { m2 = m1; m1 = v; }
                else if (v > m2) m2 = v;
            }
            gs[g] = m1 + m2;
        }
        unsigned gsel = 0;
        for (int it = 0; it < 4; it++) {
            float best = -1e30f; int bi = 0;
            for (int g = 0; g < 8; g++)
                if (!((gsel >> g) & 1) && gs[g] > best) { best = gs[g]; bi = g; }
            gsel |= 1u << bi;
        }
        float masked[32];
#pragma unroll
        for (int e = 0; e < 32; e++)
            masked[e] = ((gsel >> (e >> 2)) & 1) ? SC[e] : 0.f;
        int tki[8]; float tw[8];
        unsigned used = 0;
        for (int k = 0; k < 8; k++) {
            float best = -1e30f; int bi = 0;
            for (int e = 0; e < 32; e++)
                if (!((used >> e) & 1) && masked[e] > best) { best = masked[e]; bi = e; }
            used |= 1u << bi;
            tki[k] = bi;
            tw[k] = SS[bi];
        }
        float s = 1e-20f;
        for (int k = 0; k < 8; k++) s += tw[k];
        float inv = 2.5f / s;
        for (int k = 0; k < 8; k++) {
            int e = tki[k];
            int pos = atomicAdd(&g_cnt[e], 1);
            g_tok[e * T + pos] = t;
            g_wt [e * T + pos] = tw[k] * inv;
        }
    }
}

// ============================================================================
// GEMM tiles: BM=128, BN=64, BK=32, 256 threads = 8 warps, 2 blocks/SM.
// 3-stage cp.async ring, ONE __syncthreads per k-tile, copies 2 tiles ahead.
// Fragments via ldmatrix.x4.b16 on tf32-preconverted fp32 data.
// Smem word stride 36 -> conflict-free ldmatrix row addresses.
// Merged launches: blockIdx.z < NE = routed expert, z == NE = shared expert.
// ============================================================================
#define ASTR 36
#define GU_STAGE_W   9216            // A 4608 + Bg 2304 + Bu 2304 words
#define GU_SMEM      (3 * GU_STAGE_W * 4)
#define DN_STAGE_W   6912            // A 4608 + B 2304 words
#define DN_SMEM      (3 * DN_STAGE_W * 4)

// ---- gate+up (fused) + silu; z==NE handles the shared expert ----
__global__ void __launch_bounds__(256, 2)
gu_mma(const float* __restrict__ h,
       const float* __restrict__ Wg,  const float* __restrict__ Wu,
       const float* __restrict__ SWg, const float* __restrict__ SWu)
{
    constexpr int KD = HD;
    constexpr int NT = KD / 32;
    int z = blockIdx.z;
    bool routed = (z < NE);
    if (routed && blockIdx.x >= ID / 64) return;   // routed N=512 -> 8 n-tiles
    int cnt = routed ? g_cnt[z] : T;
    int m0  = blockIdx.y * 128;
    if (m0 >= cnt) return;
    int n0  = blockIdx.x * 64;

    extern __shared__ float smem[];
    uint32_t smem_b = smem_u32(smem);
    __shared__ int s_tok[128];

    int tid  = threadIdx.x;
    int wid  = tid >> 5;
    int lane = tid & 31;
    int wm   = wid & 3;
    int wn   = wid >> 2;

    if (routed && tid < 128) {
        int m = m0 + tid;
        s_tok[tid] = (m < cnt) ? g_tok[z * T + m] : g_tok[z * T];
    }
    __syncthreads();

    const float* Bg0 = routed ? (Wg + (size_t)z * ID * HD + (size_t)n0 * KD)
                              : (SWg + (size_t)n0 * KD);
    const float* Bu0 = routed ? (Wu + (size_t)z * ID * HD + (size_t)n0 * KD)
                              : (SWu + (size_t)n0 * KD);

    int a_row = tid >> 1;
    int a_c4  = (tid & 1) * 4;
    const float* a_src;
    if (routed) a_src = h + (size_t)s_tok[a_row] * HD;
    else        a_src = h + (size_t)(m0 + a_row) * HD;
    int b_row = tid >> 2;
    int b_c4  = (tid & 3) * 2;
    const float* bg_src = Bg0 + (size_t)b_row * KD;
    const float* bu_src = Bu0 + (size_t)b_row * KD;

    uint32_t a_dst = smem_b + (uint32_t)a_row * 144u + (uint32_t)a_c4 * 16u;
    uint32_t g_dst = smem_b + 18432u + (uint32_t)b_row * 144u + (uint32_t)b_c4 * 16u;
    uint32_t u_dst = smem_b + 27648u + (uint32_t)b_row * 144u + (uint32_t)b_c4 * 16u;

#define GU_COPY(st, k0) do { \
    uint32_t off = (uint32_t)(st) * (GU_STAGE_W * 4); \
    const float* ap = a_src  + (k0) + a_c4 * 4; \
    const float* gp = bg_src + (k0) + b_c4 * 4; \
    const float* up = bu_src + (k0) + b_c4 * 4; \
    CP16(a_dst + off,      ap);      CP16(a_dst + off + 16, ap + 4); \
    CP16(a_dst + off + 32, ap + 8);  CP16(a_dst + off + 48, ap + 12); \
    CP16(g_dst + off,      gp);      CP16(g_dst + off + 16, gp + 4); \
    CP16(u_dst + off,      up);      CP16(u_dst + off + 16, up + 4); \
} while (0)

    // ldmatrix per-lane row addresses (byte offsets within a stage)
    int lr = lane & 7, lg = lane >> 3;
    uint32_t a_off[2];
#pragma unroll
    for (int mi = 0; mi < 2; mi++) {
        int row = wm * 32 + mi * 16 + (lg & 1) * 8 + lr;
        a_off[mi] = (uint32_t)((row * ASTR + (lg >> 1) * 4) * 4);
    }
    uint32_t bg_off[2], bu_off[2];
#pragma unroll
    for (int p = 0; p < 2; p++) {
        int row = wn * 32 + p * 16 + (lg >> 1) * 8 + lr;
        int koff = (lg & 1) * 4;
        bg_off[p] = (uint32_t)((4608 + row * ASTR + koff) * 4);
        bu_off[p] = (uint32_t)((6912 + row * ASTR + koff) * 4);
    }

    float cg[2][4][4] = {}, cu[2][4][4] = {};

    // prologue: stages 0,1 in flight
    GU_COPY(0, 0);  CP_COMMIT();
    GU_COPY(1, 32); CP_COMMIT();

    int st = 0;            // kt % 3
    for (int kt = 0; kt < NT; kt++) {
        if (kt + 1 < NT) CP_WAIT(1); else CP_WAIT(0);
        __syncthreads();   // stage kt visible; all warps done reading stage (kt-1)%3

        if (kt + 2 < NT) {
            int wst = st + 2; if (wst >= 3) wst -= 3;   // (kt+2)%3 == (kt-1)%3
            GU_COPY(wst, (kt + 2) * 32);
            CP_COMMIT();
        }

        uint32_t sb = smem_b + (uint32_t)st * (GU_STAGE_W * 4);
#pragma unroll
        for (int ks = 0; ks < 4; ks++) {
            uint32_t kb = (uint32_t)ks * 32u;
            uint32_t af[2][4];
            LDSM4(af[0][0], af[0][1], af[0][2], af[0][3], sb + a_off[0] + kb);
            LDSM4(af[1][0], af[1][1], af[1][2], af[1][3], sb + a_off[1] + kb);
            uint32_t bgf[4][2], buf_[4][2];
            LDSM4(bgf[0][0], bgf[0][1], bgf[1][0], bgf[1][1], sb + bg_off[0] + kb);
            LDSM4(bgf[2][0], bgf[2][1], bgf[3][0], bgf[3][1], sb + bg_off[1] + kb);
            LDSM4(buf_[0][0], buf_[0][1], buf_[1][0], buf_[1][1], sb + bu_off[0] + kb);
            LDSM4(buf_[2][0], buf_[2][1], buf_[3][0], buf_[3][1], sb + bu_off[1] + kb);
#pragma unroll
            for (int mi = 0; mi < 2; mi++)
#pragma unroll
                for (int ni = 0; ni < 4; ni++) {
                    mma_tf32(cg[mi][ni], af[mi], bgf[ni]);
                    mma_tf32(cu[mi][ni], af[mi], buf_[ni]);
                }
        }
        if (++st == 3) st = 0;
    }
#undef GU_COPY

    // epilogue: silu(g)*u, rounded to tf32 (feeds the down GEMM)
    int gr = lane >> 2;
    int gc = (lane & 3) * 2;
    int OD = routed ? ID : HD;
    float* obase;
    if (routed) obase = g_inter + ((size_t)z * T + m0) * OD;
    else        obase = g_inter_sh + (size_t)m0 * OD;

#pragma unroll
    for (int mi = 0; mi < 2; mi++) {
        int mA = wm * 32 + mi * 16 + gr;
        int mB = mA + 8;
        bool vA = (m0 + mA) < cnt;
        bool vB = (m0 + mB) < cnt;
#pragma unroll
        for (int ni = 0; ni < 4; ni++) {
            int n = n0 + wn * 32 + ni * 8 + gc;
            float* c = cg[mi][ni];
            float* d = cu[mi][ni];
            if (vA) {
                float2 o = make_float2(
                    __uint_as_float(to_tf32(silu(c[0]) * d[0])),
                    __uint_as_float(to_tf32(silu(c[1]) * d[1])));
                *(float2*)(obase + (size_t)mA * OD + n) = o;
            }
            if (vB) {
                float2 o = make_float2(
                    __uint_as_float(to_tf32(silu(c[2]) * d[2])),
                    __uint_as_float(to_tf32(silu(c[3]) * d[3])));
                *(float2*)(obase + (size_t)mB * OD + n) = o;
            }
        }
    }
}

// ---- down-proj (merged: z<NE routed KD=512, z==NE shared KD=1024) ----
// out must be pre-zeroed; all paths atomicAdd.
__global__ void __launch_bounds__(256, 2)
down_mma(const float* __restrict__ Wd, const float* __restrict__ SWd,
         float* __restrict__ out)
{
    int z = blockIdx.z;
    bool routed = (z < NE);
    int KD = routed ? ID : HD;
    int NT = KD / 32;
    int cnt = routed ? g_cnt[z] : T;
    int m0  = blockIdx.y * 128;
    if (m0 >= cnt) return;
    int n0  = blockIdx.x * 64;

    extern __shared__ float smem[];
    uint32_t smem_b = smem_u32(smem);
    __shared__ int   s_tok[128];
    __shared__ float s_w[128];

    int tid  = threadIdx.x;
    int wid  = tid >> 5;
    int lane = tid & 31;
    int wm   = wid & 3;
    int wn   = wid >> 2;

    if (tid < 128) {
        int m = m0 + tid;
        if (routed) {
            s_tok[tid] = (m < cnt) ? g_tok[z * T + m] : 0;
            s_w[tid]   = (m < cnt) ? g_wt [z * T + m] : 0.f;
        } else {
            s_tok[tid] = m;
            s_w[tid]   = 1.f;
        }
    }
    __syncthreads();

    const float* A0 = routed ? (g_inter + ((size_t)z * T + m0) * ID)
                             : (g_inter_sh + (size_t)m0 * HD);
    const float* B0 = routed ? (Wd + (size_t)z * HD * ID + (size_t)n0 * ID)
                             : (SWd + (size_t)n0 * HD);

    int a_row = tid >> 1;
    int a_c4  = (tid & 1) * 4;
    const float* a_src = A0 + (size_t)a_row * KD;
    int b_row = tid >> 2;
    int b_c4  = (tid & 3) * 2;
    const float* b_src = B0 + (size_t)b_row * KD;

    uint32_t a_dst = smem_b + (uint32_t)a_row * 144u + (uint32_t)a_c4 * 16u;
    uint32_t b_dst = smem_b + 18432u + (uint32_t)b_row * 144u + (uint32_t)b_c4 * 16u;

#define DN_COPY(st, k0) do { \
    uint32_t off = (uint32_t)(st) * (DN_STAGE_W * 4); \
    const float* ap = a_src + (k0) + a_c4 * 4; \
    const float* bp = b_src + (k0) + b_c4 * 4; \
    CP16(a_dst + off,      ap);      CP16(a_dst + off + 16, ap + 4); \
    CP16(a_dst + off + 32, ap + 8);  CP16(a_dst + off + 48, ap + 12); \
    CP16(b_dst + off,      bp);      CP16(b_dst + off + 16, bp + 4); \
} while (0)

    int lr = lane & 7, lg = lane >> 3;
    uint32_t a_off[2];
#pragma unroll
    for (int mi = 0; mi < 2; mi++) {
        int row = wm * 32 + mi * 16 + (lg & 1) * 8 + lr;
        a_off[mi] = (uint32_t)((row * ASTR + (lg >> 1) * 4) * 4);
    }
    uint32_t bs_off[2];
#pragma unroll
    for (int p = 0; p < 2; p++) {
        int row = wn * 32 + p * 16 + (lg >> 1) * 8 + lr;
        int koff = (lg & 1) * 4;
        bs_off[p] = (uint32_t)((4608 + row * ASTR + koff) * 4);
    }

    float cc[2][4][4] = {};

    DN_COPY(0, 0);  CP_COMMIT();
    DN_COPY(1, 32); CP_COMMIT();

    int st = 0;
    for (int kt = 0; kt < NT; kt++) {
        if (kt + 1 < NT) CP_WAIT(1); else CP_WAIT(0);
        __syncthreads();

        if (kt + 2 < NT) {
            int wst = st + 2; if (wst >= 3) wst -= 3;
            DN_COPY(wst, (kt + 2) * 32);
            CP_COMMIT();
        }

        uint32_t sb = smem_b + (uint32_t)st * (DN_STAGE_W * 4);
#pragma unroll
        for (int ks = 0; ks < 4; ks++) {
            uint32_t kb = (uint32_t)ks * 32u;
            uint32_t af[2][4];
            LDSM4(af[0][0], af[0][1], af[0][2], af[0][3], sb + a_off[0] + kb);
            LDSM4(af[1][0], af[1][1], af[1][2], af[1][3], sb + a_off[1] + kb);
            uint32_t bf[4][2];
            LDSM4(bf[0][0], bf[0][1], bf[1][0], bf[1][1], sb + bs_off[0] + kb);
            LDSM4(bf[2][0], bf[2][1], bf[3][0], bf[3][1], sb + bs_off[1] + kb);
#pragma unroll
            for (int mi = 0; mi < 2; mi++)
#pragma unroll
                for (int ni = 0; ni < 4; ni++)
                    mma_tf32(cc[mi][ni], af[mi], bf[ni]);
        }
        if (++st == 3) st = 0;
    }
#undef DN_COPY

    int gr = lane >> 2;
    int gc = (lane & 3) * 2;

#pragma unroll
    for (int mi = 0; mi < 2; mi++) {
        int mA = wm * 32 + mi * 16 + gr;
        int mB = mA + 8;
        bool vA = (m0 + mA) < cnt;
        bool vB = (m0 + mB) < cnt;
#pragma unroll
        for (int ni = 0; ni < 4; ni++) {
            int n = n0 + wn * 32 + ni * 8 + gc;
            float* c = cc[mi][ni];
            if (vA) {
                float w = s_w[mA];
                float* p = out + (size_t)s_tok[mA] * HD + n;
                atomicAdd(p,     c[0] * w);
                atomicAdd(p + 1, c[1] * w);
            }
            if (vB) {
                float w = s_w[mB];
                float* p = out + (size_t)s_tok[mB] * HD + n;
                atomicAdd(p,     c[2] * w);
                atomicAdd(p + 1, c[3] * w);
            }
        }
    }
}

// ---------------- launch ----------------
extern "C" void kernel_launch(void* const* d_in, const int* in_sizes, int n_in,
                              void* d_out, int out_size) {
    const float* h       = (const float*)d_in[0];
    const float* gate_w  = (const float*)d_in[1];
    const float* gate_b  = (const float*)d_in[2];
    const float* w_gate  = (const float*)d_in[3];
    const float* w_up    = (const float*)d_in[4];
    const float* w_down  = (const float*)d_in[5];
    const float* sh_gate = (const float*)d_in[6];
    const float* sh_up   = (const float*)d_in[7];
    const float* sh_down = (const float*)d_in[8];
    float* out = (float*)d_out;

    cudaFuncSetAttribute(gu_mma,   cudaFuncAttributeMaxDynamicSharedMemorySize, GU_SMEM);
    cudaFuncSetAttribute(down_mma, cudaFuncAttributeMaxDynamicSharedMemorySize, DN_SMEM);

    float *p_wg, *p_wu, *p_wd, *p_shg, *p_shu, *p_shd, *p_hc;
    cudaGetSymbolAddress((void**)&p_wg,  g_wg);
    cudaGetSymbolAddress((void**)&p_wu,  g_wu);
    cudaGetSymbolAddress((void**)&p_wd,  g_wd);
    cudaGetSymbolAddress((void**)&p_shg, g_shg);
    cudaGetSymbolAddress((void**)&p_shu, g_shu);
    cudaGetSymbolAddress((void**)&p_shd, g_shd);
    cudaGetSymbolAddress((void**)&p_hc,  g_hc);

    zero_kernel<<<1, 32>>>();
    router_kernel<<<T / 4, 128>>>(h, gate_w, gate_b);

    const int NW4 = NE * ID * HD / 4;
    const int NS4 = 2 * ID * HD / 4;
    const int NH4 = T * HD / 4;
    cvt_tf32_kernel<<<2048, 256>>>((const float4*)w_gate,  (float4*)p_wg,  NW4);
    cvt_tf32_kernel<<<2048, 256>>>((const float4*)w_up,    (float4*)p_wu,  NW4);
    cvt_tf32_kernel<<<2048, 256>>>((const float4*)w_down,  (float4*)p_wd,  NW4);
    cvt_tf32_kernel<<<512,  256>>>((const float4*)sh_gate, (float4*)p_shg, NS4);
    cvt_tf32_kernel<<<512,  256>>>((const float4*)sh_up,   (float4*)p_shu, NS4);
    cvt_tf32_kernel<<<512,  256>>>((const float4*)sh_down, (float4*)p_shd, NS4);
    cvt_tf32_kernel<<<1024, 256>>>((const float4*)h,       (float4*)p_hc,  NH4);

    // zero out so all down-proj paths can atomicAdd (capturable, no alloc)
    cudaMemsetAsync(out, 0, (size_t)out_size * sizeof(float));

    // merged gate+up: z<32 routed (x<8 used), z==32 shared (x<16)
    gu_mma<<<dim3(16, T / 128, NE + 1), 256, GU_SMEM>>>(p_hc, p_wg, p_wu, p_shg, p_shu);
    // merged down-proj: z<32 routed (KD=512), z==32 shared (KD=1024)
    down_mma<<<dim3(HD / 64, T / 128, NE + 1), 256, DN_SMEM>>>(p_wd, p_shd, out);
}